// round 7
// baseline (speedup 1.0000x reference)
#include <cuda_runtime.h>
#include <cuda_bf16.h>
#include <math.h>

#define NN 50000
#define NE 800000
#define NG 256
#define HID 128
#define BN_EPS 1e-5f

// ---------------- persistent scratch (device globals; no allocations) ----------------
__device__ int   g_deg[NN];
__device__ int   g_fill[NN];
__device__ int   g_rowptr[NN + 1];
__device__ int   g_src[NE];
__device__ float g_invdeg[NN];
__device__ __nv_bfloat16 g_xb[(size_t)NN * 64];     // x converted to bf16
__device__ __nv_bfloat16 g_aggb[(size_t)NN * HID];  // aggregated neighbors, bf16
__device__ __nv_bfloat16 g_hpa[(size_t)NN * HID];   // pre-BN activations ping
__device__ __nv_bfloat16 g_hpb[(size_t)NN * HID];   // pre-BN activations pong
__device__ float g_colsum[3][HID];                  // fp32 column sums of raw GEMM out
__device__ float g_colsumsq[3][HID];
__device__ float g_pooled[NG * HID];                // averaged pooled features
__device__ float g_gcount[NG];

__device__ __forceinline__ int clampi(int v, int hi) { return min(max(v, 0), hi); }

__device__ __forceinline__ void mma_bf16(float c[4], const unsigned a[4], const unsigned b[2]) {
    asm volatile(
        "mma.sync.aligned.m16n8k16.row.col.f32.bf16.bf16.f32 "
        "{%0,%1,%2,%3}, {%4,%5,%6,%7}, {%8,%9}, {%0,%1,%2,%3};"
        : "+f"(c[0]), "+f"(c[1]), "+f"(c[2]), "+f"(c[3])
        : "r"(a[0]), "r"(a[1]), "r"(a[2]), "r"(a[3]), "r"(b[0]), "r"(b[1]));
}

__device__ __forceinline__ const __nv_bfloat16* srcbuf(int B) {
    return B == 0 ? g_xb : (B == 1 ? g_hpa : g_hpb);
}
__device__ __forceinline__ __nv_bfloat16* dstbuf(int B) { return B == 1 ? g_hpa : g_hpb; }

// ---------------- init: zero scratch + convert x -> bf16 ----------------
__global__ void k_init(const float* __restrict__ x) {
    int i = blockIdx.x * blockDim.x + threadIdx.x;
    if (i < NN) { g_deg[i] = 0; g_fill[i] = 0; }
    if (i < NG) g_gcount[i] = 0.0f;
    if (i < 3 * HID) { ((float*)g_colsum)[i] = 0.0f; ((float*)g_colsumsq)[i] = 0.0f; }
    if (i < NN * 16) {
        float4 v = ((const float4*)x)[i];
        __nv_bfloat162 lo = __float22bfloat162_rn(make_float2(v.x, v.y));
        __nv_bfloat162 hi = __float22bfloat162_rn(make_float2(v.z, v.w));
        uint2 o;
        o.x = *(unsigned*)&lo;
        o.y = *(unsigned*)&hi;
        ((uint2*)g_xb)[i] = o;
    }
}

// edge_index is int32 on device: ei[0..NE) = src, ei[NE..2NE) = dst
__global__ void k_deg_batch(const int* __restrict__ ei, const int* __restrict__ batch) {
    int i = blockIdx.x * blockDim.x + threadIdx.x;
    if (i < NE) atomicAdd(&g_deg[clampi(ei[NE + i], NN - 1)], 1);
    if (i < NN) atomicAdd(&g_gcount[clampi(batch[i], NG - 1)], 1.0f);
}

// single-block exclusive scan of degrees -> rowptr, plus inv_deg
__global__ void k_scan() {
    __shared__ int ssum[1024];
    int t = threadIdx.x;
    const int C = (NN + 1023) / 1024;
    int begin = t * C;
    int end   = min(begin + C, NN);
    int s = 0;
    for (int i = begin; i < end; i++) s += g_deg[i];
    ssum[t] = s;
    __syncthreads();
    for (int off = 1; off < 1024; off <<= 1) {
        int v = (t >= off) ? ssum[t - off] : 0;
        __syncthreads();
        ssum[t] += v;
        __syncthreads();
    }
    int run = (t > 0) ? ssum[t - 1] : 0;
    for (int i = begin; i < end; i++) {
        g_rowptr[i] = run;
        int d = g_deg[i];
        run += d;
        g_invdeg[i] = 1.0f / fmaxf((float)d, 1.0f);
    }
    if (t == 1023) g_rowptr[NN] = ssum[1023];
}

__global__ void k_fill(const int* __restrict__ ei) {
    int i = blockIdx.x * blockDim.x + threadIdx.x;
    if (i >= NE) return;
    int d = clampi(ei[NE + i], NN - 1);
    int p = atomicAdd(&g_fill[d], 1);
    int slot = g_rowptr[d] + p;
    if (slot < NE) g_src[slot] = clampi(ei[i], NN - 1);
}

// ---- aggregation with optional on-the-fly BN+ReLU of the source buffer ----
// agg[n][:] = inv_deg[n] * sum_{e in CSR(n)} act(in[src[e]][:]),
// act(v) = BN? relu(s_c*v + t_c) : v
template <int F, int SRCB, bool BN>
__global__ void k_aggregate(const float* __restrict__ gamma, const float* __restrict__ beta,
                            int statL) {
    const uint4* __restrict__ in = (const uint4*)srcbuf(SRCB);
    const int TPN = F / 8;                       // uint4 = 8 bf16
    int node = blockIdx.x * (256 / TPN) + threadIdx.x / TPN;
    int f = threadIdx.x % TPN;
    if (node >= NN) return;

    float s8[8], t8[8];
    if (BN) {
        const float invN = 1.0f / (float)NN;
        int c0 = f * 8;
#pragma unroll
        for (int j = 0; j < 8; j++) {
            int c = c0 + j;
            float mu = g_colsum[statL][c] * invN;
            float var = g_colsumsq[statL][c] * invN - mu * mu;
            float sc = gamma[c] * rsqrtf(var + BN_EPS);
            s8[j] = sc;
            t8[j] = beta[c] - mu * sc;
        }
    }

    int s = g_rowptr[node], e = g_rowptr[node + 1];
    float2 acc[4];
#pragma unroll
    for (int j = 0; j < 4; j++) acc[j] = make_float2(0.f, 0.f);
    for (int i = s; i < e; i++) {
        uint4 v = in[(size_t)g_src[i] * TPN + f];
        unsigned w[4] = {v.x, v.y, v.z, v.w};
#pragma unroll
        for (int j = 0; j < 4; j++) {
            float2 p = __bfloat1622float2(*(__nv_bfloat162*)&w[j]);
            if (BN) {
                p.x = fmaxf(s8[2 * j] * p.x + t8[2 * j], 0.0f);
                p.y = fmaxf(s8[2 * j + 1] * p.y + t8[2 * j + 1], 0.0f);
            }
            acc[j].x += p.x;
            acc[j].y += p.y;
        }
    }
    float id = g_invdeg[node];
    uint4 o;
    unsigned* ow = (unsigned*)&o;
#pragma unroll
    for (int j = 0; j < 4; j++) {
        __nv_bfloat162 b = __float22bfloat162_rn(make_float2(acc[j].x * id, acc[j].y * id));
        ow[j] = *(unsigned*)&b;
    }
    ((uint4*)g_aggb)[(size_t)node * TPN + f] = o;
}

// ---- bf16 dual GEMM + fused BN-stats: dst = bf16(g_aggb@W1 + act(A2)@W2) ----
// act applies previous layer's BN+ReLU on the A2 tile (A2BN). Bias absorbed by BN.
// BM=128, BN=128, BK=16; 256 threads = 8 warps (2M x 4N), warp tile 64x32, mma m16n8k16.
template <int K, int A2B, int DSTB, bool A2BN>
__global__ void __launch_bounds__(256, 2)
k_gemm_bf16(const float* __restrict__ W1, const float* __restrict__ W2, int layer,
            const float* __restrict__ gammaP, const float* __restrict__ betaP, int statP) {
    __shared__ __nv_bfloat16 As[128 * 24];   // [row][k], stride 24 bf16 (48B)
    __shared__ __nv_bfloat16 Bs[128 * 24];   // [n][k],  stride 24 bf16
    __shared__ float s_sh[128], t_sh[128];

    int tid = threadIdx.x;
    int lane = tid & 31;
    int wid = tid >> 5;
    int warp_m = wid & 1;              // 64 rows each
    int warp_n = wid >> 1;             // 32 cols each
    int g = lane >> 2;                 // 0..7
    int tg = lane & 3;                 // 0..3
    int blockRow = blockIdx.x * 128;

    if (A2BN && tid < 128) {
        const float invN = 1.0f / (float)NN;
        float mu = g_colsum[statP][tid] * invN;
        float var = g_colsumsq[statP][tid] * invN - mu * mu;
        float sc = gammaP[tid] * rsqrtf(var + BN_EPS);
        s_sh[tid] = sc;
        t_sh[tid] = betaP[tid] - mu * sc;
    }

    float acc[4][4][4];
#pragma unroll
    for (int mt = 0; mt < 4; mt++)
#pragma unroll
        for (int nt = 0; nt < 4; nt++)
#pragma unroll
            for (int q = 0; q < 4; q++) acc[mt][nt][q] = 0.0f;

    const __nv_bfloat16* Aseg = g_aggb;
    const float* Wseg = W1;
    __syncthreads();                   // s_sh/t_sh visible before seg 1 use
#pragma unroll 1
    for (int seg = 0; seg < 2; seg++) {
#pragma unroll 1
        for (int k0 = 0; k0 < K; k0 += 16) {
            // A tile: 128 rows x 16 k bf16 (uint4 = 8 bf16 per thread, 2 threads/row)
            {
                int r = tid >> 1;
                int half = tid & 1;
                int gr = blockRow + r;
                uint4 v = make_uint4(0u, 0u, 0u, 0u);
                if (gr < NN) {
                    v = *(const uint4*)(Aseg + (size_t)gr * K + k0 + half * 8);
                    if (A2BN && seg == 1) {
                        unsigned* w = (unsigned*)&v;
                        int kb = k0 + half * 8;
#pragma unroll
                        for (int j = 0; j < 4; j++) {
                            float2 p = __bfloat1622float2(*(__nv_bfloat162*)&w[j]);
                            p.x = fmaxf(s_sh[kb + 2 * j] * p.x + t_sh[kb + 2 * j], 0.0f);
                            p.y = fmaxf(s_sh[kb + 2 * j + 1] * p.y + t_sh[kb + 2 * j + 1], 0.0f);
                            __nv_bfloat162 b = __float22bfloat162_rn(p);
                            w[j] = *(unsigned*)&b;
                        }
                    }
                }
                *(uint4*)&As[r * 24 + half * 8] = v;
            }
            // B tile: W[k0+kk][n] fp32 -> Bs[n][kk] bf16 (transposed store)
            {
                int kk = tid >> 4;                 // 0..15
                int n0 = (tid & 15) * 8;           // 8 n per thread
                float4 w0 = *(const float4*)(Wseg + (size_t)(k0 + kk) * 128 + n0);
                float4 w1 = *(const float4*)(Wseg + (size_t)(k0 + kk) * 128 + n0 + 4);
                Bs[(n0 + 0) * 24 + kk] = __float2bfloat16_rn(w0.x);
                Bs[(n0 + 1) * 24 + kk] = __float2bfloat16_rn(w0.y);
                Bs[(n0 + 2) * 24 + kk] = __float2bfloat16_rn(w0.z);
                Bs[(n0 + 3) * 24 + kk] = __float2bfloat16_rn(w0.w);
                Bs[(n0 + 4) * 24 + kk] = __float2bfloat16_rn(w1.x);
                Bs[(n0 + 5) * 24 + kk] = __float2bfloat16_rn(w1.y);
                Bs[(n0 + 6) * 24 + kk] = __float2bfloat16_rn(w1.z);
                Bs[(n0 + 7) * 24 + kk] = __float2bfloat16_rn(w1.w);
            }
            __syncthreads();
            {
                unsigned a[4][4], b[4][2];
#pragma unroll
                for (int mt = 0; mt < 4; mt++) {
                    int r = warp_m * 64 + mt * 16 + g;
                    a[mt][0] = *(const unsigned*)&As[r * 24 + 2 * tg];
                    a[mt][1] = *(const unsigned*)&As[(r + 8) * 24 + 2 * tg];
                    a[mt][2] = *(const unsigned*)&As[r * 24 + 2 * tg + 8];
                    a[mt][3] = *(const unsigned*)&As[(r + 8) * 24 + 2 * tg + 8];
                }
#pragma unroll
                for (int nt = 0; nt < 4; nt++) {
                    int c = warp_n * 32 + nt * 8 + g;
                    b[nt][0] = *(const unsigned*)&Bs[c * 24 + 2 * tg];
                    b[nt][1] = *(const unsigned*)&Bs[c * 24 + 2 * tg + 8];
                }
#pragma unroll
                for (int mt = 0; mt < 4; mt++)
#pragma unroll
                    for (int nt = 0; nt < 4; nt++)
                        mma_bf16(acc[mt][nt], a[mt], b[nt]);
            }
            __syncthreads();
        }
        Aseg = srcbuf(A2B);
        Wseg = W2;
    }

    // ---- epilogue: store acc -> dst (bf16), fused per-column sum/sumsq -> atomics ----
    __nv_bfloat16* dst = dstbuf(DSTB);
#pragma unroll
    for (int mt = 0; mt < 4; mt++) {
        int r0 = blockRow + warp_m * 64 + mt * 16 + g;
#pragma unroll
        for (int nt = 0; nt < 4; nt++) {
            int c = warp_n * 32 + nt * 8 + 2 * tg;
            if (r0 < NN) {
                __nv_bfloat162 v = __float22bfloat162_rn(make_float2(acc[mt][nt][0], acc[mt][nt][1]));
                *(__nv_bfloat162*)(dst + (size_t)r0 * 128 + c) = v;
            }
            if (r0 + 8 < NN) {
                __nv_bfloat162 v = __float22bfloat162_rn(make_float2(acc[mt][nt][2], acc[mt][nt][3]));
                *(__nv_bfloat162*)(dst + (size_t)(r0 + 8) * 128 + c) = v;
            }
        }
    }
#pragma unroll
    for (int nt = 0; nt < 4; nt++) {
        float s0 = 0.f, s1 = 0.f, q0 = 0.f, q1 = 0.f;
#pragma unroll
        for (int mt = 0; mt < 4; mt++) {
            float a0 = acc[mt][nt][0], a1 = acc[mt][nt][1];
            float a2 = acc[mt][nt][2], a3 = acc[mt][nt][3];
            s0 += a0 + a2; s1 += a1 + a3;
            q0 += a0 * a0 + a2 * a2; q1 += a1 * a1 + a3 * a3;
        }
#pragma unroll
        for (int off = 4; off < 32; off <<= 1) {
            s0 += __shfl_xor_sync(0xffffffffu, s0, off);
            s1 += __shfl_xor_sync(0xffffffffu, s1, off);
            q0 += __shfl_xor_sync(0xffffffffu, q0, off);
            q1 += __shfl_xor_sync(0xffffffffu, q1, off);
        }
        if (lane < 4) {                       // g == 0
            int c = warp_n * 32 + nt * 8 + 2 * tg;
            atomicAdd(&g_colsum[layer][c], s0);
            atomicAdd(&g_colsum[layer][c + 1], s1);
            atomicAdd(&g_colsumsq[layer][c], q0);
            atomicAdd(&g_colsumsq[layer][c + 1], q1);
        }
    }
}

// ---- segmented mean-pool with on-the-fly BN+ReLU (batch sorted; no atomics) ----
// block g: pooled[g][c] = mean over its rows of relu(s_c*hpa[r][c] + t_c)
__global__ void k_pool(const float* __restrict__ gamma, const float* __restrict__ beta) {
    int g = blockIdx.x;          // 256 blocks
    int t = threadIdx.x;         // 128 threads = one column each
    __shared__ float red[128];
    // start offset = sum of counts of graphs < g
    float ps = 0.f;
    for (int j = t; j < g; j += 128) ps += g_gcount[j];
    red[t] = ps;
    __syncthreads();
    for (int off = 64; off; off >>= 1) {
        if (t < off) red[t] += red[t + off];
        __syncthreads();
    }
    int start = (int)(red[0] + 0.5f);
    float cntf = g_gcount[g];
    int cnt = (int)(cntf + 0.5f);

    const float invN = 1.0f / (float)NN;
    float mu = g_colsum[2][t] * invN;
    float var = g_colsumsq[2][t] * invN - mu * mu;
    float sc = gamma[t] * rsqrtf(var + BN_EPS);
    float tc = beta[t] - mu * sc;

    float acc = 0.0f;
    for (int r = start; r < start + cnt; r++) {
        float v = __bfloat162float(g_hpa[(size_t)r * 128 + t]);
        acc += fmaxf(sc * v + tc, 0.0f);
    }
    g_pooled[g * 128 + t] = acc / fmaxf(cntf, 1.0f);
}

// ---------------- final MLP + sigmoid ----------------
__global__ void k_mlp(const float* __restrict__ fc1W, const float* __restrict__ fc1b,
                      const float* __restrict__ fc2W, const float* __restrict__ fc2b,
                      float* __restrict__ out) {
    int g = blockIdx.x;          // 256 blocks
    int t = threadIdx.x;         // 64 threads
    __shared__ float p[128];
    __shared__ float zred[2];
    p[t]      = g_pooled[g * 128 + t];
    p[t + 64] = g_pooled[g * 128 + 64 + t];
    __syncthreads();
    float z = fc1b[t];
#pragma unroll 8
    for (int k = 0; k < 128; k++) z += p[k] * fc1W[k * 64 + t];
    z = fmaxf(z, 0.0f) * fc2W[t];
#pragma unroll
    for (int off = 16; off; off >>= 1) z += __shfl_down_sync(0xffffffffu, z, off);
    if ((t & 31) == 0) zred[t >> 5] = z;
    __syncthreads();
    if (t == 0) {
        float s = zred[0] + zred[1] + fc2b[0];
        out[g] = 1.0f / (1.0f + expf(-s));
    }
}

// ---------------- host launcher: kernel launches ONLY ----------------
extern "C" void kernel_launch(void* const* d_in, const int* in_sizes, int n_in,
                              void* d_out, int out_size) {
    const float* x     = (const float*)d_in[0];
    const int*   ei    = (const int*)d_in[1];     // int64 narrowed to int32 by harness
    const int*   batch = (const int*)d_in[2];
    const float* Wn0 = (const float*)d_in[3];
    const float* Wr0 = (const float*)d_in[4];
    const float* Wn1 = (const float*)d_in[6];
    const float* Wr1 = (const float*)d_in[7];
    const float* Wn2 = (const float*)d_in[9];
    const float* Wr2 = (const float*)d_in[10];
    const float* gamma = (const float*)d_in[12]; // [3,128]
    const float* beta  = (const float*)d_in[13];
    const float* fc1W = (const float*)d_in[14];
    const float* fc1b = (const float*)d_in[15];
    const float* fc2W = (const float*)d_in[16];
    const float* fc2b = (const float*)d_in[17];
    float* out = (float*)d_out;

    // ---- graph structure + input conversion ----
    k_init<<<(NN * 16 + 255) / 256, 256>>>(x);
    k_deg_batch<<<(NE + 255) / 256, 256>>>(ei, batch);
    k_scan<<<1, 1024>>>();
    k_fill<<<(NE + 255) / 256, 256>>>(ei);

    const int gemmGrid = (NN + 127) / 128;

    // ---- layer 0: in 64, A2 = xb (no BN), dst = hpa, stats[0] ----
    k_aggregate<64, 0, false><<<(NN + 31) / 32, 256>>>(nullptr, nullptr, 0);
    k_gemm_bf16<64, 0, 1, false><<<gemmGrid, 256>>>(Wn0, Wr0, 0, nullptr, nullptr, 0);

    // ---- layer 1: BN(stats0) applied at reads of hpa; dst = hpb, stats[1] ----
    k_aggregate<128, 1, true><<<(NN + 15) / 16, 256>>>(gamma + 0 * HID, beta + 0 * HID, 0);
    k_gemm_bf16<128, 1, 2, true><<<gemmGrid, 256>>>(Wn1, Wr1, 1, gamma + 0 * HID, beta + 0 * HID, 0);

    // ---- layer 2: BN(stats1) at reads of hpb; dst = hpa, stats[2] ----
    k_aggregate<128, 2, true><<<(NN + 15) / 16, 256>>>(gamma + 1 * HID, beta + 1 * HID, 1);
    k_gemm_bf16<128, 2, 1, true><<<gemmGrid, 256>>>(Wn2, Wr2, 2, gamma + 1 * HID, beta + 1 * HID, 1);

    // ---- pool (BN(stats2) on-the-fly, segmented) + MLP head ----
    k_pool<<<NG, 128>>>(gamma + 2 * HID, beta + 2 * HID);
    k_mlp<<<NG, 64>>>(fc1W, fc1b, fc2W, fc2b, out);
}